// round 14
// baseline (speedup 1.0000x reference)
#include <cuda_runtime.h>
#include <cuda_bf16.h>
#include <cstdint>

// out[b,i,j,d] = P1[x[b,i]][d] + P2b[x[b,j]][d]
//   P1[v]  = table[v] @ W[:128]
//   P2b[v] = table[v] @ W[128:] + bias
// VOCAB=8, EMB=128, B=4, L=512 -> out = 512 MiB f32 (store-roofline).
// R14 FINAL: restore R12, the measured optimum on every axis:
//   - single fused kernel, builder blocks 0..15 + tid-0 spin-release gate
//   - JQ=2 j-split (grid 2048x2, 128 KB/block) for tail granularity
//   - default-policy STG.128 (beats .cs: better L2 writeback batching)
//   - unroll-8 store loop (beats full unroll: paces the LSU store queue)
// Kernel 76.2us @ 6.26 TB/s = 79% of spec HBM BW (pure-write ceiling).

#define VOCAB 8
#define EMB   128
#define BATCH 4
#define SEQL  512
#define JQ    2                     // j-range halves per row
#define JLEN  (SEQL / JQ)           // 256 j's per block

__device__ float g_P[2 * VOCAB * EMB];  // P[p][v][d], bias folded into p=1
__device__ int   g_done;                // monotonic builder counter (zero-init)

__global__ __launch_bounds__(256) void fused_kernel(
        const int*   __restrict__ x,
        const float* __restrict__ table,
        const float* __restrict__ W,
        const float* __restrict__ bias,
        float4*      __restrict__ out) {
    __shared__ float4 s4[VOCAB * (EMB / 4)];   // 4 KB  S[v1][v2][d] slice
    __shared__ int    xs[JLEN];                // 1 KB  x[j] for this half
    __shared__ float  tsh[VOCAB * EMB];        // 4 KB  table (builders only)
    __shared__ float  psh[16][VOCAB][16];      // 8 KB  partials (builders only)

    const int row = blockIdx.x;                // b*512 + i
    const int q   = blockIdx.y;                // j-half 0..1
    const int bb  = row >> 9;
    const int tid = threadIdx.x;

    // ---- prologue: independent of g_P ----
    xs[tid] = x[(bb << 9) + q * JLEN + tid];   // 256 threads = JLEN
    const int v1 = x[row];
    float4* __restrict__ outp =
        out + (size_t)row * (SEQL * EMB / 4) + (size_t)q * (JLEN * EMB / 4);

    // ---- builder role: blocks (x<16, y==0) compute one (p,d-group) of g_P.
    // First 16 blocks in launch order -> wave-1 resident, no deadlock. ----
    if (row < 16 && q == 0) {
        const int p  = row & 1;                // W half
        const int dg = row >> 1;               // d-group 0..7
        const int ks = tid >> 4;               // k-slice 0..15 (8 k's each)
        const int dd = tid & 15;               // column within group
        const int d  = dg * 16 + dd;

        reinterpret_cast<float4*>(tsh)[tid] =
            reinterpret_cast<const float4*>(table)[tid];
        __syncthreads();

        float a0 = 0.f, a1 = 0.f, a2 = 0.f, a3 = 0.f,
              a4 = 0.f, a5 = 0.f, a6 = 0.f, a7 = 0.f;
        const float* __restrict__ wp = W + p * EMB * EMB + (ks * 8) * EMB + d;
        const float* __restrict__ tp = tsh + ks * 8;
        #pragma unroll
        for (int kk = 0; kk < 8; kk++) {
            const float w = wp[kk * EMB];      // 8 independent coalesced loads
            a0 += tp[0 * EMB + kk] * w;  a1 += tp[1 * EMB + kk] * w;
            a2 += tp[2 * EMB + kk] * w;  a3 += tp[3 * EMB + kk] * w;
            a4 += tp[4 * EMB + kk] * w;  a5 += tp[5 * EMB + kk] * w;
            a6 += tp[6 * EMB + kk] * w;  a7 += tp[7 * EMB + kk] * w;
        }
        psh[ks][0][dd] = a0; psh[ks][1][dd] = a1;
        psh[ks][2][dd] = a2; psh[ks][3][dd] = a3;
        psh[ks][4][dd] = a4; psh[ks][5][dd] = a5;
        psh[ks][6][dd] = a6; psh[ks][7][dd] = a7;
        __syncthreads();

        if (tid < VOCAB * 16) {                // reduce 16 k-slices
            const int v  = tid >> 4;
            const int d2 = tid & 15;
            float s = (p == 1) ? bias[dg * 16 + d2] : 0.0f;
            #pragma unroll
            for (int k2 = 0; k2 < 16; k2++) s += psh[k2][v][d2];
            g_P[p * (VOCAB * EMB) + v * EMB + dg * 16 + d2] = s;
        }
        __threadfence();                       // release P before counting
        __syncthreads();
        if (tid == 0) atomicAdd(&g_done, 1);
    }

    // ---- gate (tid-0 funnel): first launch enforces build->read order;
    // replays see g_done >= 16 already (builders rewrite identical values).
    if (tid == 0) {
        while (*(volatile int*)&g_done < 16) __nanosleep(64);
        __threadfence();                       // acquire (one thread only)
    }
    __syncthreads();

    // ---- assemble S[v1] slice: s4[v2*32+c] = P1[v1][c] + P2b[v2][c] ----
    {
        const int v2 = tid >> 5;
        const int c  = tid & 31;
        const float4* __restrict__ P4 = (const float4*)g_P;
        const float4 a  = P4[(v1 << 5) + c];
        const float4 pb = P4[(VOCAB << 5) + (v2 << 5) + c];
        s4[tid] = make_float4(a.x + pb.x, a.y + pb.y, a.z + pb.z, a.w + pb.w);
    }
    __syncthreads();

    // ---- stream 128 KB: 32 iters of coalesced STG.128 (default policy),
    // unroll 8. Each warp-iteration covers one j: xs[j] broadcast,
    // conflict-free LDS.128.
    #pragma unroll 8
    for (int it = 0; it < 32; it++) {
        const int idx = (it << 8) + tid;       // 0..8191
        const int j   = idx >> 5;              // constant within a warp
        const int cc  = idx & 31;
        outp[idx] = s4[(xs[j] << 5) + cc];     // plain STG.E.128
    }
}

// ---------------------------------------------------------------------------
// Inputs (metadata order): x int32[2048], table f32[1024], W f32[32768],
// b f32[128]. Output: f32[134217728].
// ---------------------------------------------------------------------------
extern "C" void kernel_launch(void* const* d_in, const int* in_sizes, int n_in,
                              void* d_out, int out_size) {
    const int*   x     = (const int*)  d_in[0];
    const float* table = (const float*)d_in[1];
    const float* W     = (const float*)d_in[2];
    const float* bias  = (const float*)d_in[3];
    float4*      out   = (float4*)d_out;

    dim3 grid(BATCH * SEQL, JQ);
    fused_kernel<<<grid, 256>>>(x, table, W, bias, out);
}

// round 15
// speedup vs baseline: 1.0120x; 1.0120x over previous
#include <cuda_runtime.h>
#include <cuda_bf16.h>
#include <cstdint>

// out[b,i,j,d] = P1[x[b,i]][d] + P2b[x[b,j]][d]
//   P1[v]  = table[v] @ W[:128]
//   P2b[v] = table[v] @ W[128:] + bias
// VOCAB=8, EMB=128, B=4, L=512 -> out = 512 MiB f32 (store-roofline).
// FINAL (== R12/R14, measured optimum on every axis):
//   - single fused kernel, builder blocks 0..15 + tid-0 spin-release gate
//   - JQ=2 j-split (grid 2048x2, 128 KB/block) for tail granularity
//   - default-policy STG.128 (L2 writeback batching)
//   - unroll-8 store loop (paces the LSU store queue across warps)
// Kernel 76.2-77.4us @ ~6.2 TB/s = 77-79% of spec HBM BW (write ceiling).

#define VOCAB 8
#define EMB   128
#define BATCH 4
#define SEQL  512
#define JQ    2                     // j-range halves per row
#define JLEN  (SEQL / JQ)           // 256 j's per block

__device__ float g_P[2 * VOCAB * EMB];  // P[p][v][d], bias folded into p=1
__device__ int   g_done;                // monotonic builder counter (zero-init)

__global__ __launch_bounds__(256) void fused_kernel(
        const int*   __restrict__ x,
        const float* __restrict__ table,
        const float* __restrict__ W,
        const float* __restrict__ bias,
        float4*      __restrict__ out) {
    __shared__ float4 s4[VOCAB * (EMB / 4)];   // 4 KB  S[v1][v2][d] slice
    __shared__ int    xs[JLEN];                // 1 KB  x[j] for this half
    __shared__ float  tsh[VOCAB * EMB];        // 4 KB  table (builders only)
    __shared__ float  psh[16][VOCAB][16];      // 8 KB  partials (builders only)

    const int row = blockIdx.x;                // b*512 + i
    const int q   = blockIdx.y;                // j-half 0..1
    const int bb  = row >> 9;
    const int tid = threadIdx.x;

    // ---- prologue: independent of g_P ----
    xs[tid] = x[(bb << 9) + q * JLEN + tid];   // 256 threads = JLEN
    const int v1 = x[row];
    float4* __restrict__ outp =
        out + (size_t)row * (SEQL * EMB / 4) + (size_t)q * (JLEN * EMB / 4);

    // ---- builder role: blocks (x<16, y==0) compute one (p,d-group) of g_P.
    // First 16 blocks in launch order -> wave-1 resident, no deadlock. ----
    if (row < 16 && q == 0) {
        const int p  = row & 1;                // W half
        const int dg = row >> 1;               // d-group 0..7
        const int ks = tid >> 4;               // k-slice 0..15 (8 k's each)
        const int dd = tid & 15;               // column within group
        const int d  = dg * 16 + dd;

        reinterpret_cast<float4*>(tsh)[tid] =
            reinterpret_cast<const float4*>(table)[tid];
        __syncthreads();

        float a0 = 0.f, a1 = 0.f, a2 = 0.f, a3 = 0.f,
              a4 = 0.f, a5 = 0.f, a6 = 0.f, a7 = 0.f;
        const float* __restrict__ wp = W + p * EMB * EMB + (ks * 8) * EMB + d;
        const float* __restrict__ tp = tsh + ks * 8;
        #pragma unroll
        for (int kk = 0; kk < 8; kk++) {
            const float w = wp[kk * EMB];      // 8 independent coalesced loads
            a0 += tp[0 * EMB + kk] * w;  a1 += tp[1 * EMB + kk] * w;
            a2 += tp[2 * EMB + kk] * w;  a3 += tp[3 * EMB + kk] * w;
            a4 += tp[4 * EMB + kk] * w;  a5 += tp[5 * EMB + kk] * w;
            a6 += tp[6 * EMB + kk] * w;  a7 += tp[7 * EMB + kk] * w;
        }
        psh[ks][0][dd] = a0; psh[ks][1][dd] = a1;
        psh[ks][2][dd] = a2; psh[ks][3][dd] = a3;
        psh[ks][4][dd] = a4; psh[ks][5][dd] = a5;
        psh[ks][6][dd] = a6; psh[ks][7][dd] = a7;
        __syncthreads();

        if (tid < VOCAB * 16) {                // reduce 16 k-slices
            const int v  = tid >> 4;
            const int d2 = tid & 15;
            float s = (p == 1) ? bias[dg * 16 + d2] : 0.0f;
            #pragma unroll
            for (int k2 = 0; k2 < 16; k2++) s += psh[k2][v][d2];
            g_P[p * (VOCAB * EMB) + v * EMB + dg * 16 + d2] = s;
        }
        __threadfence();                       // release P before counting
        __syncthreads();
        if (tid == 0) atomicAdd(&g_done, 1);
    }

    // ---- gate (tid-0 funnel): first launch enforces build->read order;
    // replays see g_done >= 16 already (builders rewrite identical values).
    if (tid == 0) {
        while (*(volatile int*)&g_done < 16) __nanosleep(64);
        __threadfence();                       // acquire (one thread only)
    }
    __syncthreads();

    // ---- assemble S[v1] slice: s4[v2*32+c] = P1[v1][c] + P2b[v2][c] ----
    {
        const int v2 = tid >> 5;
        const int c  = tid & 31;
        const float4* __restrict__ P4 = (const float4*)g_P;
        const float4 a  = P4[(v1 << 5) + c];
        const float4 pb = P4[(VOCAB << 5) + (v2 << 5) + c];
        s4[tid] = make_float4(a.x + pb.x, a.y + pb.y, a.z + pb.z, a.w + pb.w);
    }
    __syncthreads();

    // ---- stream 128 KB: 32 iters of coalesced STG.128 (default policy),
    // unroll 8. Each warp-iteration covers one j: xs[j] broadcast,
    // conflict-free LDS.128.
    #pragma unroll 8
    for (int it = 0; it < 32; it++) {
        const int idx = (it << 8) + tid;       // 0..8191
        const int j   = idx >> 5;              // constant within a warp
        const int cc  = idx & 31;
        outp[idx] = s4[(xs[j] << 5) + cc];     // plain STG.E.128
    }
}

// ---------------------------------------------------------------------------
// Inputs (metadata order): x int32[2048], table f32[1024], W f32[32768],
// b f32[128]. Output: f32[134217728].
// ---------------------------------------------------------------------------
extern "C" void kernel_launch(void* const* d_in, const int* in_sizes, int n_in,
                              void* d_out, int out_size) {
    const int*   x     = (const int*)  d_in[0];
    const float* table = (const float*)d_in[1];
    const float* W     = (const float*)d_in[2];
    const float* bias  = (const float*)d_in[3];
    float4*      out   = (float4*)d_out;

    dim3 grid(BATCH * SEQL, JQ);
    fused_kernel<<<grid, 256>>>(x, table, W, bias, out);
}

// round 16
// speedup vs baseline: 1.0231x; 1.0110x over previous
#include <cuda_runtime.h>
#include <cuda_bf16.h>
#include <cstdint>

// out[b,i,j,d] = P1[x[b,i]][d] + P2b[x[b,j]][d]
//   P1[v]  = table[v] @ W[:128]
//   P2b[v] = table[v] @ W[128:] + bias
// VOCAB=8, EMB=128, B=4, L=512 -> out = 512 MiB f32 (store-roofline).
// FINAL (converged; measured optimum on every explored axis):
//   - single fused kernel, builder blocks 0..15 + tid-0 spin-release gate
//   - JQ=2 j-split (grid 2048x2, 128 KB/block) for tail granularity
//   - default-policy STG.128 (L2 writeback batching beats .cs)
//   - unroll-8 store loop (pacing beats full front-batching)
// Kernel 76.2-77.4us @ ~6.25 TB/s = 78-79% of spec HBM BW (write ceiling).

#define VOCAB 8
#define EMB   128
#define BATCH 4
#define SEQL  512
#define JQ    2                     // j-range halves per row
#define JLEN  (SEQL / JQ)           // 256 j's per block

__device__ float g_P[2 * VOCAB * EMB];  // P[p][v][d], bias folded into p=1
__device__ int   g_done;                // monotonic builder counter (zero-init)

__global__ __launch_bounds__(256) void fused_kernel(
        const int*   __restrict__ x,
        const float* __restrict__ table,
        const float* __restrict__ W,
        const float* __restrict__ bias,
        float4*      __restrict__ out) {
    __shared__ float4 s4[VOCAB * (EMB / 4)];   // 4 KB  S[v1][v2][d] slice
    __shared__ int    xs[JLEN];                // 1 KB  x[j] for this half
    __shared__ float  tsh[VOCAB * EMB];        // 4 KB  table (builders only)
    __shared__ float  psh[16][VOCAB][16];      // 8 KB  partials (builders only)

    const int row = blockIdx.x;                // b*512 + i
    const int q   = blockIdx.y;                // j-half 0..1
    const int bb  = row >> 9;
    const int tid = threadIdx.x;

    // ---- prologue: independent of g_P ----
    xs[tid] = x[(bb << 9) + q * JLEN + tid];   // 256 threads = JLEN
    const int v1 = x[row];
    float4* __restrict__ outp =
        out + (size_t)row * (SEQL * EMB / 4) + (size_t)q * (JLEN * EMB / 4);

    // ---- builder role: blocks (x<16, y==0) compute one (p,d-group) of g_P.
    // First 16 blocks in launch order -> wave-1 resident, no deadlock. ----
    if (row < 16 && q == 0) {
        const int p  = row & 1;                // W half
        const int dg = row >> 1;               // d-group 0..7
        const int ks = tid >> 4;               // k-slice 0..15 (8 k's each)
        const int dd = tid & 15;               // column within group
        const int d  = dg * 16 + dd;

        reinterpret_cast<float4*>(tsh)[tid] =
            reinterpret_cast<const float4*>(table)[tid];
        __syncthreads();

        float a0 = 0.f, a1 = 0.f, a2 = 0.f, a3 = 0.f,
              a4 = 0.f, a5 = 0.f, a6 = 0.f, a7 = 0.f;
        const float* __restrict__ wp = W + p * EMB * EMB + (ks * 8) * EMB + d;
        const float* __restrict__ tp = tsh + ks * 8;
        #pragma unroll
        for (int kk = 0; kk < 8; kk++) {
            const float w = wp[kk * EMB];      // 8 independent coalesced loads
            a0 += tp[0 * EMB + kk] * w;  a1 += tp[1 * EMB + kk] * w;
            a2 += tp[2 * EMB + kk] * w;  a3 += tp[3 * EMB + kk] * w;
            a4 += tp[4 * EMB + kk] * w;  a5 += tp[5 * EMB + kk] * w;
            a6 += tp[6 * EMB + kk] * w;  a7 += tp[7 * EMB + kk] * w;
        }
        psh[ks][0][dd] = a0; psh[ks][1][dd] = a1;
        psh[ks][2][dd] = a2; psh[ks][3][dd] = a3;
        psh[ks][4][dd] = a4; psh[ks][5][dd] = a5;
        psh[ks][6][dd] = a6; psh[ks][7][dd] = a7;
        __syncthreads();

        if (tid < VOCAB * 16) {                // reduce 16 k-slices
            const int v  = tid >> 4;
            const int d2 = tid & 15;
            float s = (p == 1) ? bias[dg * 16 + d2] : 0.0f;
            #pragma unroll
            for (int k2 = 0; k2 < 16; k2++) s += psh[k2][v][d2];
            g_P[p * (VOCAB * EMB) + v * EMB + dg * 16 + d2] = s;
        }
        __threadfence();                       // release P before counting
        __syncthreads();
        if (tid == 0) atomicAdd(&g_done, 1);
    }

    // ---- gate (tid-0 funnel): first launch enforces build->read order;
    // replays see g_done >= 16 already (builders rewrite identical values).
    if (tid == 0) {
        while (*(volatile int*)&g_done < 16) __nanosleep(64);
        __threadfence();                       // acquire (one thread only)
    }
    __syncthreads();

    // ---- assemble S[v1] slice: s4[v2*32+c] = P1[v1][c] + P2b[v2][c] ----
    {
        const int v2 = tid >> 5;
        const int c  = tid & 31;
        const float4* __restrict__ P4 = (const float4*)g_P;
        const float4 a  = P4[(v1 << 5) + c];
        const float4 pb = P4[(VOCAB << 5) + (v2 << 5) + c];
        s4[tid] = make_float4(a.x + pb.x, a.y + pb.y, a.z + pb.z, a.w + pb.w);
    }
    __syncthreads();

    // ---- stream 128 KB: 32 iters of coalesced STG.128 (default policy),
    // unroll 8. Each warp-iteration covers one j: xs[j] broadcast,
    // conflict-free LDS.128.
    #pragma unroll 8
    for (int it = 0; it < 32; it++) {
        const int idx = (it << 8) + tid;       // 0..8191
        const int j   = idx >> 5;              // constant within a warp
        const int cc  = idx & 31;
        outp[idx] = s4[(xs[j] << 5) + cc];     // plain STG.E.128
    }
}

// ---------------------------------------------------------------------------
// Inputs (metadata order): x int32[2048], table f32[1024], W f32[32768],
// b f32[128]. Output: f32[134217728].
// ---------------------------------------------------------------------------
extern "C" void kernel_launch(void* const* d_in, const int* in_sizes, int n_in,
                              void* d_out, int out_size) {
    const int*   x     = (const int*)  d_in[0];
    const float* table = (const float*)d_in[1];
    const float* W     = (const float*)d_in[2];
    const float* bias  = (const float*)d_in[3];
    float4*      out   = (float4*)d_out;

    dim3 grid(BATCH * SEQL, JQ);
    fused_kernel<<<grid, 256>>>(x, table, W, bias, out);
}